// round 8
// baseline (speedup 1.0000x reference)
#include <cuda_runtime.h>
#include <cuda_fp16.h>
#include <mma.h>
#include <cstdint>
#include <math.h>

using namespace nvcuda;

#define B_    32
#define V_    32000
#define EMB_  512
#define H_    1024
#define T_    100
#define KG    2048
#define GROWS 4096
#define KSPL  8
#define GRB   64
#define LRB   64
#define NBLK  (V_ / LRB)     // 500
#define KC    64
#define STG   3
#define NPWB  64             // pwrite blocks
#define DELTA 0.05f

#define ALD   72             // A smem row stride (halves)
#define BLD   40             // B smem row stride (halves)

// ---------------- static device state ----------------
__device__ __align__(128) half  g_wc_hi[GROWS * KG];   // PERMUTED rows: row' = hid*4+gate
__device__ __align__(128) half  g_wc_lo[GROWS * KG];
__device__ __align__(128) half  g_wo[(size_t)V_ * H_];
__device__ __align__(128) half  g_x_hi[KG * B_];
__device__ __align__(128) half  g_x_lo[KG * B_];
__device__ __align__(128) float g_part[(size_t)KSPL * GROWS * B_];
__device__ __align__(128) float g_logits[B_ * V_];
__device__ __align__(128) float g_c[H_ * B_];
__device__ __align__(128) float g_hf[B_ * H_];
__device__ int    g_s[B_];
__device__ float2 g_cM[B_ * NBLK];
__device__ float4 g_cT[B_ * NBLK];
__device__ float  g_gm[B_], g_gi[B_];
__device__ int    g_gcnt[GROWS / GRB];   // zero-init
__device__ int    g_lcnt;                // zero-init

// ---------------- helpers ----------------
__device__ __forceinline__ void cp16(void* sdst, const void* gsrc) {
  uint32_t d = (uint32_t)__cvta_generic_to_shared(sdst);
  asm volatile("cp.async.cg.shared.global [%0], [%1], 16;\n" :: "r"(d), "l"(gsrc));
}
#define CP_COMMIT() asm volatile("cp.async.commit_group;\n" ::: "memory")
#define CP_WAIT(n)  asm volatile("cp.async.wait_group %0;\n" :: "n"(n) : "memory")

__host__ __device__ inline void tf2x32(uint32_t k0, uint32_t k1, uint32_t x0, uint32_t x1,
                                       uint32_t &o0, uint32_t &o1) {
  uint32_t ks2 = k0 ^ k1 ^ 0x1BD11BDAu;
  x0 += k0; x1 += k1;
#define TF_R(r) do { x0 += x1; x1 = (x1 << (r)) | (x1 >> (32 - (r))); x1 ^= x0; } while (0)
  TF_R(13); TF_R(15); TF_R(26); TF_R(6);
  x0 += k1;  x1 += ks2 + 1u;
  TF_R(17); TF_R(29); TF_R(16); TF_R(24);
  x0 += ks2; x1 += k0 + 2u;
  TF_R(13); TF_R(15); TF_R(26); TF_R(6);
  x0 += k0;  x1 += k1 + 3u;
  TF_R(17); TF_R(29); TF_R(16); TF_R(24);
  x0 += k1;  x1 += ks2 + 4u;
  TF_R(13); TF_R(15); TF_R(26); TF_R(6);
  x0 += ks2; x1 += k0 + 5u;
#undef TF_R
  o0 = x0; o1 = x1;
}

__device__ __forceinline__ float gumbel_of(uint32_t k0, uint32_t k1, uint32_t i) {
  uint32_t a, b;
  tf2x32(k0, k1, 0u, i, a, b);
  uint32_t bits = a ^ b;
  float u = __uint_as_float((bits >> 9) | 0x3f800000u) - 1.0f;
  const float tiny = 1.17549435e-38f;
  float val = fmaxf(tiny, u * (1.0f - tiny) + tiny);
  return -logf(-logf(val));
}

__device__ __forceinline__ float sigm(float x) { return 1.0f / (1.0f + expf(-x)); }

__device__ __forceinline__ void merge2(float &v1, int &i1, float &v2, int &i2,
                                       float b1, int j1, float b2, int j2) {
  float n1, n2; int m1, m2;
  bool bf = (b1 > v1) || (b1 == v1 && j1 < i1);
  if (bf) { n1 = b1; m1 = j1; bool tk = (v1 > b2) || (v1 == b2 && i1 < j2);
            n2 = tk ? v1 : b2; m2 = tk ? i1 : j2; }
  else    { n1 = v1; m1 = i1; bool tk = (b1 > v2) || (b1 == v2 && j1 < i2);
            n2 = tk ? b1 : v2; m2 = tk ? j1 : i2; }
  v1 = n1; i1 = m1; v2 = n2; i2 = m2;
}

// ---------------- conversion / init ----------------
// permuted combined weights: output row r' = hid*4 + gate; source row = gate*1024 + hid
__global__ void k_conv_comb(const float* __restrict__ w_ih, const float* __restrict__ w_hh) {
  int np = GROWS * KG / 2;
  for (int p = blockIdx.x * blockDim.x + threadIdx.x; p < np; p += gridDim.x * blockDim.x) {
    int rp = p >> 10, kp = (p & 1023) * 2;
    int hid = rp >> 2, gate = rp & 3;
    int sr = gate * 1024 + hid;
    float v0, v1;
    if (kp < 1024) { v0 = __ldcs(w_ih + sr * 1024 + kp); v1 = __ldcs(w_ih + sr * 1024 + kp + 1); }
    else           { v0 = __ldcs(w_hh + sr * 1024 + kp - 1024); v1 = __ldcs(w_hh + sr * 1024 + kp - 1023); }
    half h0 = __float2half(v0), h1 = __float2half(v1);
    half2 hi = __halves2half2(h0, h1);
    half2 lo = __halves2half2(__float2half(v0 - __half2float(h0)),
                              __float2half(v1 - __half2float(h1)));
    size_t off = (size_t)rp * KG + kp;
    *(half2*)&g_wc_hi[off] = hi;
    *(half2*)&g_wc_lo[off] = lo;
  }
}
__global__ void k_conv_wout(const float* __restrict__ w) {
  size_t np = (size_t)V_ * H_ / 2;
  for (size_t p = blockIdx.x * blockDim.x + threadIdx.x; p < np; p += (size_t)gridDim.x * blockDim.x) {
    float v0 = __ldcs(w + 2 * p), v1 = __ldcs(w + 2 * p + 1);
    *(half2*)&g_wo[2 * p] = __halves2half2(__float2half(v0), __float2half(v1));
  }
}
__global__ void k_init(const float* __restrict__ z, const int* __restrict__ sid,
                       const float* __restrict__ emb) {
  int idx = blockIdx.x * blockDim.x + threadIdx.x;
  if (idx < H_ * B_) {
    g_c[idx] = 0.0f;
    g_x_hi[H_ * B_ + idx] = __float2half(0.0f);
    g_x_lo[H_ * B_ + idx] = __float2half(0.0f);
    int b = idx & 31, hid = idx >> 5;
    g_hf[b * H_ + hid] = 0.0f;
  }
  if (idx < EMB_ * B_) {
    int b = idx & 31, k = idx >> 5;
    float v = z[b * EMB_ + k];
    half hi = __float2half(v);
    g_x_hi[(EMB_ + k) * B_ + b] = hi;
    g_x_lo[(EMB_ + k) * B_ + b] = __float2half(v - __half2float(hi));
    int tok = sid ? sid[0] : 0;
    float e = emb[tok * EMB_ + k];
    half ehi = __float2half(e);
    g_x_hi[k * B_ + b] = ehi;
    g_x_lo[k * B_ + b] = __float2half(e - __half2float(ehi));
  }
  if (idx < B_) g_s[idx] = sid ? sid[0] : 0;
}

// ---------------- p-writer body (for step tp) ----------------
__device__ __forceinline__ void pwrite_body(float* __restrict__ outP, int tp, int blk, int nblk) {
  int tid = threadIdx.x;
  for (int e = blk * 128 + tid; e < B_ * V_; e += nblk * 128) {
    int b = e / V_, v = e - b * V_;
    float p = expf(__ldcs(&g_logits[e]) - g_gm[b]) * g_gi[b];
    __stcs(&outP[((size_t)b * T_ + tp) * V_ + v], p);
  }
}

// ------ K1: gates GEMM + fused cell (last split-K block) + pwrite(t-1) -------
// grid (64, 9): y<8 -> gates split-K slice; y==8 -> pwrite blocks
__global__ void k_gates(const float* __restrict__ bias, float* __restrict__ outP, int t) {
  extern __shared__ half sm[];
  if (blockIdx.y == KSPL) {                 // p-writer slice
    if (t > 0) pwrite_body(outP, t - 1, blockIdx.x, NPWB);
    return;
  }
  half* As = sm;
  half* Bh = sm + STG * GRB * ALD;
  half* Bl = Bh + STG * KC * BLD;
  const int grp  = blockIdx.x;
  const int row0 = grp * GRB;
  const int ks = blockIdx.y;
  const int tid = threadIdx.x, w = tid >> 5;
  const bool hiPhase = ks < 4;
  const half* Wsrc = hiPhase ? g_wc_hi : g_wc_lo;
  const int kk0 = (ks & 3) * 512;
  const int NCHK = 512 / KC;   // 8

  wmma::fragment<wmma::accumulator, 16, 16, 16, float> fc0, fc1;
  wmma::fill_fragment(fc0, 0.0f); wmma::fill_fragment(fc1, 0.0f);

  auto issue = [&](int c) {
    int s = c % STG, kk = kk0 + c * KC;
    half* as = As + s * GRB * ALD;
#pragma unroll
    for (int j = 0; j < 4; j++) {
      int idx = tid + 128 * j, r = idx >> 3, cc = idx & 7;
      cp16(as + r * ALD + cc * 8, Wsrc + (size_t)(row0 + r) * KG + kk + cc * 8);
    }
    half* bh = Bh + s * KC * BLD;
    half* bl = Bl + s * KC * BLD;
#pragma unroll
    for (int j = 0; j < 2; j++) {
      int idx = tid + 128 * j, r = idx >> 2, cc = idx & 3;
      cp16(bh + r * BLD + cc * 8, g_x_hi + (kk + r) * B_ + cc * 8);
      if (hiPhase)
        cp16(bl + r * BLD + cc * 8, g_x_lo + (kk + r) * B_ + cc * 8);
    }
    CP_COMMIT();
  };

  issue(0); issue(1); issue(2);

  for (int c = 0; c < NCHK; c++) {
    if (c + STG < NCHK) { CP_WAIT(2); } else { CP_WAIT(0); }
    __syncthreads();
    int s = c % STG;
    half* as = As + s * GRB * ALD;
    half* bh = Bh + s * KC * BLD;
    half* bl = Bl + s * KC * BLD;
    wmma::fragment<wmma::matrix_a, 16, 16, 16, half, wmma::row_major> fa;
    wmma::fragment<wmma::matrix_b, 16, 16, 16, half, wmma::row_major> fb0, fb1;
#pragma unroll
    for (int k4 = 0; k4 < KC / 16; k4++) {
      wmma::load_matrix_sync(fa, as + (w * 16) * ALD + k4 * 16, ALD);
      wmma::load_matrix_sync(fb0, bh + (k4 * 16) * BLD + 0, BLD);
      wmma::load_matrix_sync(fb1, bh + (k4 * 16) * BLD + 16, BLD);
      wmma::mma_sync(fc0, fa, fb0, fc0);
      wmma::mma_sync(fc1, fa, fb1, fc1);
      if (hiPhase) {
        wmma::load_matrix_sync(fb0, bl + (k4 * 16) * BLD + 0, BLD);
        wmma::load_matrix_sync(fb1, bl + (k4 * 16) * BLD + 16, BLD);
        wmma::mma_sync(fc0, fa, fb0, fc0);
        wmma::mma_sync(fc1, fa, fb1, fc1);
      }
    }
    __syncthreads();
    if (c + STG < NCHK) issue(c + STG);
  }
  float* dst = g_part + ((size_t)ks * GROWS + row0 + w * 16) * B_;
  wmma::store_matrix_sync(dst, fc0, B_, wmma::mem_row_major);
  wmma::store_matrix_sync(dst + 16, fc1, B_, wmma::mem_row_major);

  // ---- completion counting; last block of this group runs the LSTM cell ----
  __threadfence();
  __syncthreads();
  __shared__ int s_last;
  if (tid == 0) {
    int r = atomicAdd(&g_gcnt[grp], 1);
    s_last = (r == KSPL - 1);
    if (s_last) g_gcnt[grp] = 0;
  }
  __syncthreads();
  if (!s_last) return;
  __threadfence();   // acquire: make all groups' partials visible

#pragma unroll
  for (int i = 0; i < 4; i++) {
    int idx = tid + 128 * i;          // 512 cells: 16 hids x 32 batch
    int b = idx & 31, hl = idx >> 5;
    int hid = grp * 16 + hl;
    float a0 = 0.f, a1 = 0.f, a2 = 0.f, a3 = 0.f;
#pragma unroll
    for (int kk = 0; kk < KSPL; kk++) {
      const float* p = g_part + (size_t)kk * GROWS * B_ + (size_t)(row0 + hl * 4) * B_;
      a0 += p[0 * B_ + b];
      a1 += p[1 * B_ + b];
      a2 += p[2 * B_ + b];
      a3 += p[3 * B_ + b];
    }
    float ig = a0 + bias[hid];
    float fg = a1 + bias[H_ + hid];
    float gg = a2 + bias[2 * H_ + hid];
    float og = a3 + bias[3 * H_ + hid];
    float c  = g_c[hid * B_ + b];
    float cn = sigm(fg) * c + sigm(ig) * tanhf(gg);
    float hn = sigm(og) * tanhf(cn);
    g_c[hid * B_ + b] = cn;
    g_hf[b * H_ + hid] = hn;
    half hi = __float2half(hn);
    g_x_hi[(H_ + hid) * B_ + b] = hi;
    g_x_lo[(H_ + hid) * B_ + b] = __float2half(hn - __half2float(hi));
  }
}

// ------ K2: logits GEMM + stats; last block runs finalize --------------------
__global__ void k_logits(const float* __restrict__ bout, const float* __restrict__ wout,
                         const float* __restrict__ emb, float* outS,
                         int t, uint32_t k0, uint32_t k1) {
  __shared__ half As[STG][LRB * ALD];
  __shared__ half Bs[STG][KC * BLD];
  const int blk = blockIdx.x;
  const int row0 = blk * LRB;
  const int tid = threadIdx.x, w = tid >> 5;
  const half* Bsrc = g_x_hi + H_ * B_;
  const int NCHK = H_ / KC;   // 16

  wmma::fragment<wmma::accumulator, 16, 16, 16, float> fc0, fc1;
  wmma::fill_fragment(fc0, 0.0f); wmma::fill_fragment(fc1, 0.0f);

  auto issue = [&](int c) {
    int s = c % STG, kk = c * KC;
#pragma unroll
    for (int j = 0; j < 4; j++) {
      int idx = tid + 128 * j, r = idx >> 3, cc = idx & 7;
      cp16(&As[s][r * ALD + cc * 8], g_wo + (size_t)(row0 + r) * H_ + kk + cc * 8);
    }
#pragma unroll
    for (int j = 0; j < 2; j++) {
      int idx = tid + 128 * j, r = idx >> 2, cc = idx & 3;
      cp16(&Bs[s][r * BLD + cc * 8], Bsrc + (kk + r) * B_ + cc * 8);
    }
    CP_COMMIT();
  };

  issue(0); issue(1); issue(2);

  for (int c = 0; c < NCHK; c++) {
    if (c + STG < NCHK) { CP_WAIT(2); } else { CP_WAIT(0); }
    __syncthreads();
    int s = c % STG;
    wmma::fragment<wmma::matrix_a, 16, 16, 16, half, wmma::row_major> fa;
    wmma::fragment<wmma::matrix_b, 16, 16, 16, half, wmma::row_major> fb0, fb1;
#pragma unroll
    for (int k4 = 0; k4 < KC / 16; k4++) {
      wmma::load_matrix_sync(fa, &As[s][(w * 16) * ALD + k4 * 16], ALD);
      wmma::load_matrix_sync(fb0, &Bs[s][(k4 * 16) * BLD + 0], BLD);
      wmma::load_matrix_sync(fb1, &Bs[s][(k4 * 16) * BLD + 16], BLD);
      wmma::mma_sync(fc0, fa, fb0, fc0);
      wmma::mma_sync(fc1, fa, fb1, fc1);
    }
    __syncthreads();
    if (c + STG < NCHK) issue(c + STG);
  }

  float* Ls = (float*)&As[0][0];
  __syncthreads();
  wmma::store_matrix_sync(&Ls[(w * 16) * 36 + 0],  fc0, 36, wmma::mem_row_major);
  wmma::store_matrix_sync(&Ls[(w * 16) * 36 + 16], fc1, 36, wmma::mem_row_major);
  __syncthreads();

  for (int i = tid; i < LRB * B_; i += 128) {
    int b = i >> 6, r = i & 63;
    float lb = Ls[r * 36 + b] + bout[row0 + r];
    Ls[r * 36 + b] = lb;
    __stcs(&g_logits[b * V_ + row0 + r], lb);
  }
  __syncthreads();

  int c = tid >> 2, sub = tid & 3;
  float m = -INFINITY, s = 0.0f, v1 = -INFINITY, v2 = -INFINITY;
  int i1 = 0x7fffffff, i2 = 0x7fffffff;
  for (int r = sub; r < LRB; r += 4) {
    float lb = Ls[r * 36 + c];
    if (lb > m) { s = s * expf(m - lb) + 1.0f; m = lb; } else s += expf(lb - m);
    int v = row0 + r;
    float tv = lb + gumbel_of(k0, k1, (uint32_t)(c * V_ + v));
    if (tv > v1 || (tv == v1 && v < i1)) { v2 = v1; i2 = i1; v1 = tv; i1 = v; }
    else if (tv > v2 || (tv == v2 && v < i2)) { v2 = tv; i2 = v; }
  }
#pragma unroll
  for (int o = 1; o <= 2; o <<= 1) {
    float om = __shfl_xor_sync(0xffffffffu, m, o);
    float os = __shfl_xor_sync(0xffffffffu, s, o);
    float M = fmaxf(m, om);
    s = s * expf(m - M) + os * expf(om - M); m = M;
    float b1 = __shfl_xor_sync(0xffffffffu, v1, o);
    int   j1 = __shfl_xor_sync(0xffffffffu, i1, o);
    float b2 = __shfl_xor_sync(0xffffffffu, v2, o);
    int   j2 = __shfl_xor_sync(0xffffffffu, i2, o);
    merge2(v1, i1, v2, i2, b1, j1, b2, j2);
  }
  if (sub == 0) {
    g_cM[c * NBLK + blk] = make_float2(m, s);
    g_cT[c * NBLK + blk] = make_float4(v1, __int_as_float(i1), v2, __int_as_float(i2));
  }

  // ---- completion counting; last block runs the finalize ----
  __threadfence();
  __syncthreads();
  __shared__ int s_last;
  if (tid == 0) {
    int r = atomicAdd(&g_lcnt, 1);
    s_last = (r == NBLK - 1);
    if (s_last) g_lcnt = 0;
  }
  __syncthreads();
  if (!s_last) return;
  __threadfence();   // acquire all blocks' stats

  // --- finalize (128 threads): per-batch gm/gi, exact token, next embed ---
  __shared__ float rm[128], rs[128], r1[128];
  __shared__ int   q1[128];
  for (int b = 0; b < B_; b++) {
    float m2 = -INFINITY, s2 = 0.0f, w1 = -INFINITY;
    int x1 = 0x7fffffff;
    for (int j = tid; j < NBLK; j += 128) {
      float2 a = g_cM[b * NBLK + j];
      float M = fmaxf(m2, a.x);
      s2 = s2 * expf(m2 - M) + a.y * expf(a.x - M); m2 = M;
      float4 tt = g_cT[b * NBLK + j];
      float d2 = -INFINITY; int di = 0x7fffffff;
      merge2(w1, x1, d2, di, tt.x, __float_as_int(tt.y), tt.z, __float_as_int(tt.w));
    }
    rm[tid] = m2; rs[tid] = s2; r1[tid] = w1; q1[tid] = x1;
    __syncthreads();
    for (int off = 64; off; off >>= 1) {
      if (tid < off) {
        float mA = rm[tid], mB = rm[tid + off];
        float M = fmaxf(mA, mB);
        rm[tid] = M;
        rs[tid] = rs[tid] * expf(mA - M) + rs[tid + off] * expf(mB - M);
        float bv = r1[tid + off]; int bi = q1[tid + off];
        if (bv > r1[tid] || (bv == r1[tid] && bi < q1[tid])) { r1[tid] = bv; q1[tid] = bi; }
      }
      __syncthreads();
    }
    if (tid == 0) { g_gm[b] = rm[0]; g_gi[b] = 1.0f / rs[0]; }
    float gtop = r1[0];
    __syncthreads();

    __shared__ int ncand;
    __shared__ int cands[64];
    __shared__ double cval[64];
    __shared__ int    cidx[64];
    __shared__ int    s_tok;
    if (tid == 0) ncand = 0;
    __syncthreads();
    float thr = gtop - DELTA;
    for (int j = tid; j < NBLK; j += 128) {
      float4 a = g_cT[b * NBLK + j];
      if (a.x >= thr) { int p = atomicAdd(&ncand, 1); if (p < 64) cands[p] = __float_as_int(a.y); }
      if (a.z >= thr) { int p = atomicAdd(&ncand, 1); if (p < 64) cands[p] = __float_as_int(a.w); }
    }
    __syncthreads();
    int n = ncand < 64 ? ncand : 64;
    int ww = tid >> 5, lane = tid & 31;
    for (int ci = ww; ci < n; ci += 4) {
      int v = cands[ci];
      const float* wr = wout + (size_t)v * H_;
      const float* hr = g_hf + b * H_;
      double acc = 0.0;
      for (int j = lane; j < H_; j += 32) acc += (double)__ldcs(wr + j) * (double)hr[j];
      for (int o = 16; o; o >>= 1) acc += __shfl_down_sync(0xffffffffu, acc, o);
      if (lane == 0) {
        cval[ci] = acc + (double)bout[v] + (double)gumbel_of(k0, k1, (uint32_t)(b * V_ + v));
        cidx[ci] = v;
      }
    }
    __syncthreads();
    if (tid == 0) {
      double bv = -1e300; int bi = 0x7fffffff;
      for (int ci = 0; ci < n; ci++)
        if (cval[ci] > bv || (cval[ci] == bv && cidx[ci] < bi)) { bv = cval[ci]; bi = cidx[ci]; }
      s_tok = bi;
      g_s[b] = bi;
      if (outS) outS[b * T_ + t] = (float)bi;
    }
    __syncthreads();
    int tok = s_tok;
    for (int k = tid; k < EMB_; k += 128) {
      float val = emb[tok * EMB_ + k];
      half hi = __float2half(val);
      g_x_hi[k * B_ + b] = hi;
      g_x_lo[k * B_ + b] = __float2half(val - __half2float(hi));
    }
    __syncthreads();
  }
}

// ---- standalone tail p-writer for t = T-1 ----
__global__ void k_ptail(float* __restrict__ outP) {
  pwrite_body(outP, T_ - 1, blockIdx.x, gridDim.x);
}

// ---------------- host ----------------
extern "C" void kernel_launch(void* const* d_in, const int* in_sizes, int n_in,
                              void* d_out, int out_size) {
  const float* z     = (const float*)d_in[0];
  const float* emb   = (const float*)d_in[1];
  const float* w_ih  = (const float*)d_in[2];
  const float* w_hh  = (const float*)d_in[3];
  const float* bias  = (const float*)d_in[4];
  const float* w_out = (const float*)d_in[5];
  const float* b_out = (const float*)d_in[6];
  const int*   sid   = (n_in > 7) ? (const int*)d_in[7] : nullptr;

  float* out  = (float*)d_out;
  float* outS = out;
  float* outP = out + B_ * T_;
  if (out_size == B_ * T_ * V_) { outS = nullptr; outP = out; }

  const int gatesSmem = (STG * GRB * ALD + 2 * STG * KC * BLD) * (int)sizeof(half);
  cudaFuncSetAttribute(k_gates, cudaFuncAttributeMaxDynamicSharedMemorySize, gatesSmem);

  k_conv_comb<<<512, 256>>>(w_ih, w_hh);
  k_conv_wout<<<2048, 256>>>(w_out);
  k_init<<<(H_ * B_ + 255) / 256, 256>>>(z, sid, emb);

  for (int t = 0; t < T_; ++t) {
    uint32_t fk0, fk1;
    tf2x32(0u, 42u, 0u, (uint32_t)t, fk0, fk1);
    k_gates<<<dim3(GROWS / GRB, KSPL + 1), 128, gatesSmem>>>(bias, outP, t);
    k_logits<<<NBLK, 128>>>(b_out, w_out, emb, outS, t, fk0, fk1);
  }
  k_ptail<<<NPWB, 128>>>(outP);
}

// round 9
// speedup vs baseline: 5.1402x; 5.1402x over previous
#include <cuda_runtime.h>
#include <cuda_fp16.h>
#include <mma.h>
#include <cstdint>
#include <math.h>

using namespace nvcuda;

#define B_    32
#define V_    32000
#define EMB_  512
#define H_    1024
#define T_    100
#define KG    2048
#define GROWS 4096
#define KSPL  8
#define GRB   64
#define LRB   64
#define NBLK  (V_ / LRB)     // 500
#define KC    64
#define STG   3
#define NPWB  64
#define DELTA 0.05f

#define ALD   72             // A smem row stride (halves)
#define BLD   40             // B smem row stride (halves)

// ---------------- static device state ----------------
__device__ __align__(128) half  g_wc_hi[GROWS * KG];   // PERMUTED rows: row' = hid*4+gate
__device__ __align__(128) half  g_wc_lo[GROWS * KG];
__device__ __align__(128) half  g_wo[(size_t)V_ * H_];
__device__ __align__(128) half  g_x_hi[KG * B_];
__device__ __align__(128) half  g_x_lo[KG * B_];
__device__ __align__(128) float g_part[(size_t)KSPL * GROWS * B_];
__device__ __align__(128) float g_logits[B_ * V_];
__device__ __align__(128) float g_c[H_ * B_];
__device__ __align__(128) float g_hf[B_ * H_];
__device__ int    g_s[B_];
__device__ float2 g_cM[B_ * NBLK];
__device__ float4 g_cT[B_ * NBLK];
__device__ float  g_gm[B_], g_gi[B_];
__device__ int    g_gcnt[GROWS / GRB];   // zero-init

// ---------------- helpers ----------------
__device__ __forceinline__ void cp16(void* sdst, const void* gsrc) {
  uint32_t d = (uint32_t)__cvta_generic_to_shared(sdst);
  asm volatile("cp.async.cg.shared.global [%0], [%1], 16;\n" :: "r"(d), "l"(gsrc));
}
#define CP_COMMIT() asm volatile("cp.async.commit_group;\n" ::: "memory")
#define CP_WAIT(n)  asm volatile("cp.async.wait_group %0;\n" :: "n"(n) : "memory")

__device__ __forceinline__ void stcs4(float* gdst, float4 v) { __stcs((float4*)gdst, v); }

__host__ __device__ inline void tf2x32(uint32_t k0, uint32_t k1, uint32_t x0, uint32_t x1,
                                       uint32_t &o0, uint32_t &o1) {
  uint32_t ks2 = k0 ^ k1 ^ 0x1BD11BDAu;
  x0 += k0; x1 += k1;
#define TF_R(r) do { x0 += x1; x1 = (x1 << (r)) | (x1 >> (32 - (r))); x1 ^= x0; } while (0)
  TF_R(13); TF_R(15); TF_R(26); TF_R(6);
  x0 += k1;  x1 += ks2 + 1u;
  TF_R(17); TF_R(29); TF_R(16); TF_R(24);
  x0 += ks2; x1 += k0 + 2u;
  TF_R(13); TF_R(15); TF_R(26); TF_R(6);
  x0 += k0;  x1 += k1 + 3u;
  TF_R(17); TF_R(29); TF_R(16); TF_R(24);
  x0 += k1;  x1 += ks2 + 4u;
  TF_R(13); TF_R(15); TF_R(26); TF_R(6);
  x0 += ks2; x1 += k0 + 5u;
#undef TF_R
  o0 = x0; o1 = x1;
}

__device__ __forceinline__ float gumbel_of(uint32_t k0, uint32_t k1, uint32_t i) {
  uint32_t a, b;
  tf2x32(k0, k1, 0u, i, a, b);
  uint32_t bits = a ^ b;
  float u = __uint_as_float((bits >> 9) | 0x3f800000u) - 1.0f;
  const float tiny = 1.17549435e-38f;
  float val = fmaxf(tiny, u * (1.0f - tiny) + tiny);
  return -logf(-logf(val));
}

__device__ __forceinline__ float sigm(float x) { return 1.0f / (1.0f + expf(-x)); }

__device__ __forceinline__ void merge2(float &v1, int &i1, float &v2, int &i2,
                                       float b1, int j1, float b2, int j2) {
  float n1, n2; int m1, m2;
  bool bf = (b1 > v1) || (b1 == v1 && j1 < i1);
  if (bf) { n1 = b1; m1 = j1; bool tk = (v1 > b2) || (v1 == b2 && i1 < j2);
            n2 = tk ? v1 : b2; m2 = tk ? i1 : j2; }
  else    { n1 = v1; m1 = i1; bool tk = (b1 > v2) || (b1 == v2 && j1 < i2);
            n2 = tk ? b1 : v2; m2 = tk ? j1 : i2; }
  v1 = n1; i1 = m1; v2 = n2; i2 = m2;
}

// ---------------- conversion / init ----------------
// permuted combined weights: output row r' = hid*4 + gate; source row = gate*1024 + hid
__global__ void k_conv_comb(const float* __restrict__ w_ih, const float* __restrict__ w_hh) {
  int np = GROWS * KG / 2;
  for (int p = blockIdx.x * blockDim.x + threadIdx.x; p < np; p += gridDim.x * blockDim.x) {
    int rp = p >> 10, kp = (p & 1023) * 2;
    int hid = rp >> 2, gate = rp & 3;
    int sr = gate * 1024 + hid;
    float v0, v1;
    if (kp < 1024) { v0 = __ldcs(w_ih + sr * 1024 + kp); v1 = __ldcs(w_ih + sr * 1024 + kp + 1); }
    else           { v0 = __ldcs(w_hh + sr * 1024 + kp - 1024); v1 = __ldcs(w_hh + sr * 1024 + kp - 1023); }
    half h0 = __float2half(v0), h1 = __float2half(v1);
    half2 hi = __halves2half2(h0, h1);
    half2 lo = __halves2half2(__float2half(v0 - __half2float(h0)),
                              __float2half(v1 - __half2float(h1)));
    size_t off = (size_t)rp * KG + kp;
    *(half2*)&g_wc_hi[off] = hi;
    *(half2*)&g_wc_lo[off] = lo;
  }
}
__global__ void k_conv_wout(const float* __restrict__ w) {
  size_t np = (size_t)V_ * H_ / 2;
  for (size_t p = blockIdx.x * blockDim.x + threadIdx.x; p < np; p += (size_t)gridDim.x * blockDim.x) {
    float v0 = __ldcs(w + 2 * p), v1 = __ldcs(w + 2 * p + 1);
    *(half2*)&g_wo[2 * p] = __halves2half2(__float2half(v0), __float2half(v1));
  }
}
__global__ void k_init(const float* __restrict__ z, const int* __restrict__ sid,
                       const float* __restrict__ emb) {
  int idx = blockIdx.x * blockDim.x + threadIdx.x;
  if (idx < H_ * B_) {
    g_c[idx] = 0.0f;
    g_x_hi[H_ * B_ + idx] = __float2half(0.0f);
    g_x_lo[H_ * B_ + idx] = __float2half(0.0f);
    int b = idx & 31, hid = idx >> 5;
    g_hf[b * H_ + hid] = 0.0f;
  }
  if (idx < EMB_ * B_) {
    int b = idx & 31, k = idx >> 5;
    float v = z[b * EMB_ + k];
    half hi = __float2half(v);
    g_x_hi[(EMB_ + k) * B_ + b] = hi;
    g_x_lo[(EMB_ + k) * B_ + b] = __float2half(v - __half2float(hi));
    int tok = sid ? sid[0] : 0;
    float e = emb[tok * EMB_ + k];
    half ehi = __float2half(e);
    g_x_hi[k * B_ + b] = ehi;
    g_x_lo[k * B_ + b] = __float2half(e - __half2float(ehi));
  }
  if (idx < B_) g_s[idx] = sid ? sid[0] : 0;
}

// ---------------- p-writer body ----------------
__device__ __forceinline__ void pwrite_body(float* __restrict__ outP, int tp, int blk, int nblk) {
  int tid = threadIdx.x;
  for (int e = blk * 128 + tid; e < B_ * V_; e += nblk * 128) {
    int b = e / V_, v = e - b * V_;
    float p = expf(__ldcs(&g_logits[e]) - g_gm[b]) * g_gi[b];
    __stcs(&outP[((size_t)b * T_ + tp) * V_ + v], p);
  }
}

// ------ K1: gates GEMM + fused cell (last split-K block) + pwrite(t-1) -------
// grid (64, 9): y<8 -> gates split-K slice; y==8 -> pwrite slice
__global__ void k_gates(const float* __restrict__ bias, float* __restrict__ outP, int t) {
  extern __shared__ half sm[];
  if (blockIdx.y == KSPL) {
    if (t > 0) pwrite_body(outP, t - 1, blockIdx.x, NPWB);
    return;
  }
  half* As = sm;
  half* Bh = sm + STG * GRB * ALD;
  half* Bl = Bh + STG * KC * BLD;
  const int grp  = blockIdx.x;
  const int row0 = grp * GRB;
  const int ks = blockIdx.y;
  const int tid = threadIdx.x, w = tid >> 5;
  const bool hiPhase = ks < 4;
  const half* Wsrc = hiPhase ? g_wc_hi : g_wc_lo;
  const int kk0 = (ks & 3) * 512;
  const int NCHK = 512 / KC;   // 8

  wmma::fragment<wmma::accumulator, 16, 16, 16, float> fc0, fc1;
  wmma::fill_fragment(fc0, 0.0f); wmma::fill_fragment(fc1, 0.0f);

  auto issue = [&](int c) {
    int s = c % STG, kk = kk0 + c * KC;
    half* as = As + s * GRB * ALD;
#pragma unroll
    for (int j = 0; j < 4; j++) {
      int idx = tid + 128 * j, r = idx >> 3, cc = idx & 7;
      cp16(as + r * ALD + cc * 8, Wsrc + (size_t)(row0 + r) * KG + kk + cc * 8);
    }
    half* bh = Bh + s * KC * BLD;
    half* bl = Bl + s * KC * BLD;
#pragma unroll
    for (int j = 0; j < 2; j++) {
      int idx = tid + 128 * j, r = idx >> 2, cc = idx & 3;
      cp16(bh + r * BLD + cc * 8, g_x_hi + (kk + r) * B_ + cc * 8);
      if (hiPhase)
        cp16(bl + r * BLD + cc * 8, g_x_lo + (kk + r) * B_ + cc * 8);
    }
    CP_COMMIT();
  };

  issue(0); issue(1); issue(2);

  for (int c = 0; c < NCHK; c++) {
    if (c + STG < NCHK) { CP_WAIT(2); } else { CP_WAIT(0); }
    __syncthreads();
    int s = c % STG;
    half* as = As + s * GRB * ALD;
    half* bh = Bh + s * KC * BLD;
    half* bl = Bl + s * KC * BLD;
    wmma::fragment<wmma::matrix_a, 16, 16, 16, half, wmma::row_major> fa;
    wmma::fragment<wmma::matrix_b, 16, 16, 16, half, wmma::row_major> fb0, fb1;
#pragma unroll
    for (int k4 = 0; k4 < KC / 16; k4++) {
      wmma::load_matrix_sync(fa, as + (w * 16) * ALD + k4 * 16, ALD);
      wmma::load_matrix_sync(fb0, bh + (k4 * 16) * BLD + 0, BLD);
      wmma::load_matrix_sync(fb1, bh + (k4 * 16) * BLD + 16, BLD);
      wmma::mma_sync(fc0, fa, fb0, fc0);
      wmma::mma_sync(fc1, fa, fb1, fc1);
      if (hiPhase) {
        wmma::load_matrix_sync(fb0, bl + (k4 * 16) * BLD + 0, BLD);
        wmma::load_matrix_sync(fb1, bl + (k4 * 16) * BLD + 16, BLD);
        wmma::mma_sync(fc0, fa, fb0, fc0);
        wmma::mma_sync(fc1, fa, fb1, fc1);
      }
    }
    __syncthreads();
    if (c + STG < NCHK) issue(c + STG);
  }

  // partial store staged through smem, written evict-first (protect L2 weights)
  float* Ps = (float*)sm;   // 64 rows x 32 cols = 8KB, aliases As (all loads drained)
  __syncthreads();
  wmma::store_matrix_sync(&Ps[(w * 16) * 32 + 0],  fc0, 32, wmma::mem_row_major);
  wmma::store_matrix_sync(&Ps[(w * 16) * 32 + 16], fc1, 32, wmma::mem_row_major);
  __syncthreads();
  {
    float* dst = g_part + ((size_t)ks * GROWS + row0) * B_;
#pragma unroll
    for (int i = 0; i < 4; i++) {
      int q = tid + 128 * i;            // 512 float4 = 2048 floats
      stcs4(dst + q * 4, *(float4*)&Ps[q * 4]);
    }
  }

  // completion counting; last block of this group runs the LSTM cell
  __threadfence();
  __syncthreads();
  __shared__ int s_last;
  if (tid == 0) {
    int r = atomicAdd(&g_gcnt[grp], 1);
    s_last = (r == KSPL - 1);
    if (s_last) g_gcnt[grp] = 0;
  }
  __syncthreads();
  if (!s_last) return;
  __threadfence();

#pragma unroll
  for (int i = 0; i < 4; i++) {
    int idx = tid + 128 * i;            // 512 cells: 16 hids x 32 batch
    int b = idx & 31, hl = idx >> 5;
    int hid = grp * 16 + hl;
    float a0 = 0.f, a1 = 0.f, a2 = 0.f, a3 = 0.f;
#pragma unroll
    for (int kk = 0; kk < KSPL; kk++) {
      const float* p = g_part + (size_t)kk * GROWS * B_ + (size_t)(row0 + hl * 4) * B_;
      a0 += __ldcs(p + 0 * B_ + b);
      a1 += __ldcs(p + 1 * B_ + b);
      a2 += __ldcs(p + 2 * B_ + b);
      a3 += __ldcs(p + 3 * B_ + b);
    }
    float ig = a0 + bias[hid];
    float fg = a1 + bias[H_ + hid];
    float gg = a2 + bias[2 * H_ + hid];
    float og = a3 + bias[3 * H_ + hid];
    float c  = g_c[hid * B_ + b];
    float cn = sigm(fg) * c + sigm(ig) * tanhf(gg);
    float hn = sigm(og) * tanhf(cn);
    g_c[hid * B_ + b] = cn;
    g_hf[b * H_ + hid] = hn;
    half hi = __float2half(hn);
    g_x_hi[(H_ + hid) * B_ + b] = hi;
    g_x_lo[(H_ + hid) * B_ + b] = __float2half(hn - __half2float(hi));
  }
}

// ------ K2: logits GEMM + chunk stats.  grid 500, block 128 ------------------
__global__ void k_logits(const float* __restrict__ bout, uint32_t k0, uint32_t k1) {
  __shared__ half As[STG][LRB * ALD];
  __shared__ half Bs[STG][KC * BLD];
  const int blk = blockIdx.x;
  const int row0 = blk * LRB;
  const int tid = threadIdx.x, w = tid >> 5;
  const half* Bsrc = g_x_hi + H_ * B_;
  const int NCHK = H_ / KC;   // 16

  wmma::fragment<wmma::accumulator, 16, 16, 16, float> fc0, fc1;
  wmma::fill_fragment(fc0, 0.0f); wmma::fill_fragment(fc1, 0.0f);

  auto issue = [&](int c) {
    int s = c % STG, kk = c * KC;
#pragma unroll
    for (int j = 0; j < 4; j++) {
      int idx = tid + 128 * j, r = idx >> 3, cc = idx & 7;
      cp16(&As[s][r * ALD + cc * 8], g_wo + (size_t)(row0 + r) * H_ + kk + cc * 8);
    }
#pragma unroll
    for (int j = 0; j < 2; j++) {
      int idx = tid + 128 * j, r = idx >> 2, cc = idx & 3;
      cp16(&Bs[s][r * BLD + cc * 8], Bsrc + (kk + r) * B_ + cc * 8);
    }
    CP_COMMIT();
  };

  issue(0); issue(1); issue(2);

  for (int c = 0; c < NCHK; c++) {
    if (c + STG < NCHK) { CP_WAIT(2); } else { CP_WAIT(0); }
    __syncthreads();
    int s = c % STG;
    wmma::fragment<wmma::matrix_a, 16, 16, 16, half, wmma::row_major> fa;
    wmma::fragment<wmma::matrix_b, 16, 16, 16, half, wmma::row_major> fb0, fb1;
#pragma unroll
    for (int k4 = 0; k4 < KC / 16; k4++) {
      wmma::load_matrix_sync(fa, &As[s][(w * 16) * ALD + k4 * 16], ALD);
      wmma::load_matrix_sync(fb0, &Bs[s][(k4 * 16) * BLD + 0], BLD);
      wmma::load_matrix_sync(fb1, &Bs[s][(k4 * 16) * BLD + 16], BLD);
      wmma::mma_sync(fc0, fa, fb0, fc0);
      wmma::mma_sync(fc1, fa, fb1, fc1);
    }
    __syncthreads();
    if (c + STG < NCHK) issue(c + STG);
  }

  float* Ls = (float*)&As[0][0];
  __syncthreads();
  wmma::store_matrix_sync(&Ls[(w * 16) * 36 + 0],  fc0, 36, wmma::mem_row_major);
  wmma::store_matrix_sync(&Ls[(w * 16) * 36 + 16], fc1, 36, wmma::mem_row_major);
  __syncthreads();

  for (int i = tid; i < LRB * B_; i += 128) {
    int b = i >> 6, r = i & 63;
    float lb = Ls[r * 36 + b] + bout[row0 + r];
    Ls[r * 36 + b] = lb;
    __stcs(&g_logits[b * V_ + row0 + r], lb);
  }
  __syncthreads();

  int c = tid >> 2, sub = tid & 3;
  float m = -INFINITY, s = 0.0f, v1 = -INFINITY, v2 = -INFINITY;
  int i1 = 0x7fffffff, i2 = 0x7fffffff;
  for (int r = sub; r < LRB; r += 4) {
    float lb = Ls[r * 36 + c];
    if (lb > m) { s = s * expf(m - lb) + 1.0f; m = lb; } else s += expf(lb - m);
    int v = row0 + r;
    float tv = lb + gumbel_of(k0, k1, (uint32_t)(c * V_ + v));
    if (tv > v1 || (tv == v1 && v < i1)) { v2 = v1; i2 = i1; v1 = tv; i1 = v; }
    else if (tv > v2 || (tv == v2 && v < i2)) { v2 = tv; i2 = v; }
  }
#pragma unroll
  for (int o = 1; o <= 2; o <<= 1) {
    float om = __shfl_xor_sync(0xffffffffu, m, o);
    float os = __shfl_xor_sync(0xffffffffu, s, o);
    float M = fmaxf(m, om);
    s = s * expf(m - M) + os * expf(om - M); m = M;
    float b1 = __shfl_xor_sync(0xffffffffu, v1, o);
    int   j1 = __shfl_xor_sync(0xffffffffu, i1, o);
    float b2 = __shfl_xor_sync(0xffffffffu, v2, o);
    int   j2 = __shfl_xor_sync(0xffffffffu, i2, o);
    merge2(v1, i1, v2, i2, b1, j1, b2, j2);
  }
  if (sub == 0) {
    __stcs(&g_cM[c * NBLK + blk], make_float2(m, s));
    __stcs(&g_cT[c * NBLK + blk], make_float4(v1, __int_as_float(i1), v2, __int_as_float(i2)));
  }
}

// ---- K3: finalize per batch (parallel).  grid 32, block 256 -----------------
__global__ void k_final(const float* __restrict__ wout, const float* __restrict__ bout,
                        const float* __restrict__ emb, float* outS,
                        int t, uint32_t k0, uint32_t k1) {
  int b = blockIdx.x, tid = threadIdx.x;
  __shared__ float rm[256], rs[256], r1[256];
  __shared__ int   q1[256];
  float m = -INFINITY, s = 0.0f, v1 = -INFINITY;
  int i1 = 0x7fffffff;
  for (int j = tid; j < NBLK; j += 256) {
    float2 a = __ldcs(&g_cM[b * NBLK + j]);
    float M = fmaxf(m, a.x);
    s = s * expf(m - M) + a.y * expf(a.x - M); m = M;
    float4 tt = __ldcs(&g_cT[b * NBLK + j]);
    float d2 = -INFINITY; int di = 0x7fffffff;
    merge2(v1, i1, d2, di, tt.x, __float_as_int(tt.y), tt.z, __float_as_int(tt.w));
  }
  rm[tid] = m; rs[tid] = s; r1[tid] = v1; q1[tid] = i1;
  __syncthreads();
  for (int off = 128; off; off >>= 1) {
    if (tid < off) {
      float mA = rm[tid], mB = rm[tid + off];
      float M = fmaxf(mA, mB);
      rm[tid] = M;
      rs[tid] = rs[tid] * expf(mA - M) + rs[tid + off] * expf(mB - M);
      float bv = r1[tid + off]; int bi = q1[tid + off];
      if (bv > r1[tid] || (bv == r1[tid] && bi < q1[tid])) { r1[tid] = bv; q1[tid] = bi; }
    }
    __syncthreads();
  }
  if (tid == 0) { g_gm[b] = rm[0]; g_gi[b] = 1.0f / rs[0]; }
  float gtop = r1[0];
  __syncthreads();

  __shared__ int ncand;
  __shared__ int cands[64];
  __shared__ double cval[64];
  __shared__ int    cidx[64];
  __shared__ int    s_tok;
  if (tid == 0) ncand = 0;
  __syncthreads();
  float thr = gtop - DELTA;
  for (int j = tid; j < NBLK; j += 256) {
    float4 a = __ldcs(&g_cT[b * NBLK + j]);
    if (a.x >= thr) { int p = atomicAdd(&ncand, 1); if (p < 64) cands[p] = __float_as_int(a.y); }
    if (a.z >= thr) { int p = atomicAdd(&ncand, 1); if (p < 64) cands[p] = __float_as_int(a.w); }
  }
  __syncthreads();
  int n = ncand < 64 ? ncand : 64;
  int w = tid >> 5, lane = tid & 31;
  for (int ci = w; ci < n; ci += 8) {
    int v = cands[ci];
    const float4* wr4 = (const float4*)(wout + (size_t)v * H_);
    const float4* hr4 = (const float4*)(g_hf + b * H_);
    double acc = 0.0;
#pragma unroll
    for (int j = 0; j < 8; j++) {                  // 8 x float4 per lane, MLP 8
      float4 a4 = __ldg(wr4 + lane + 32 * j);
      float4 b4 = hr4[lane + 32 * j];
      acc += (double)a4.x * b4.x + (double)a4.y * b4.y
           + (double)a4.z * b4.z + (double)a4.w * b4.w;
    }
    for (int o = 16; o; o >>= 1) acc += __shfl_down_sync(0xffffffffu, acc, o);
    if (lane == 0) {
      cval[ci] = acc + (double)bout[v] + (double)gumbel_of(k0, k1, (uint32_t)(b * V_ + v));
      cidx[ci] = v;
    }
  }
  __syncthreads();
  if (tid == 0) {
    double bv = -1e300; int bi = 0x7fffffff;
    for (int ci = 0; ci < n; ci++)
      if (cval[ci] > bv || (cval[ci] == bv && cidx[ci] < bi)) { bv = cval[ci]; bi = cidx[ci]; }
    s_tok = bi;
    g_s[b] = bi;
    if (outS) outS[b * T_ + t] = (float)bi;
  }
  __syncthreads();
  int tok = s_tok;
  for (int k = tid; k < EMB_; k += 256) {
    float val = emb[tok * EMB_ + k];
    half hi = __float2half(val);
    g_x_hi[k * B_ + b] = hi;
    g_x_lo[k * B_ + b] = __float2half(val - __half2float(hi));
  }
}

// ---- tail p-writer for t = T-1 ----
__global__ void k_ptail(float* __restrict__ outP) {
  pwrite_body(outP, T_ - 1, blockIdx.x, gridDim.x);
}

// ---------------- host ----------------
extern "C" void kernel_launch(void* const* d_in, const int* in_sizes, int n_in,
                              void* d_out, int out_size) {
  const float* z     = (const float*)d_in[0];
  const float* emb   = (const float*)d_in[1];
  const float* w_ih  = (const float*)d_in[2];
  const float* w_hh  = (const float*)d_in[3];
  const float* bias  = (const float*)d_in[4];
  const float* w_out = (const float*)d_in[5];
  const float* b_out = (const float*)d_in[6];
  const int*   sid   = (n_in > 7) ? (const int*)d_in[7] : nullptr;

  float* out  = (float*)d_out;
  float* outS = out;
  float* outP = out + B_ * T_;
  if (out_size == B_ * T_ * V_) { outS = nullptr; outP = out; }

  const int gatesSmem = (STG * GRB * ALD + 2 * STG * KC * BLD) * (int)sizeof(half);
  cudaFuncSetAttribute(k_gates, cudaFuncAttributeMaxDynamicSharedMemorySize, gatesSmem);

  k_conv_comb<<<512, 256>>>(w_ih, w_hh);
  k_conv_wout<<<2048, 256>>>(w_out);
  k_init<<<(H_ * B_ + 255) / 256, 256>>>(z, sid, emb);

  for (int t = 0; t < T_; ++t) {
    uint32_t fk0, fk1;
    tf2x32(0u, 42u, 0u, (uint32_t)t, fk0, fk1);
    k_gates<<<dim3(GROWS / GRB, KSPL + 1), 128, gatesSmem>>>(bias, outP, t);
    k_logits<<<NBLK, 128>>>(b_out, fk0, fk1);
    k_final<<<B_, 256>>>(w_out, b_out, emb, outS, t, fk0, fk1);
  }
  k_ptail<<<NPWB, 128>>>(outP);
}

// round 10
// speedup vs baseline: 7.0635x; 1.3742x over previous
#include <cuda_runtime.h>
#include <cuda_fp16.h>
#include <mma.h>
#include <cstdint>
#include <math.h>

using namespace nvcuda;

#define B_    32
#define V_    32000
#define EMB_  512
#define H_    1024
#define T_    100
#define KG    2048
#define GROWS 4096
#define KSPL  4              // split-K for gates (virtual K = 4096, 1024/slice)
#define GRB   64
#define LRB   64
#define NBLK  (V_ / LRB)     // 500
#define KC    64
#define STG   3
#define NPB   16
#define VCH   (V_ / NPB)
#define DELTA 0.05f

#define ALD   72             // A smem row stride (halves)
#define BLD   40             // B smem row stride (halves)

// ---------------- static device state ----------------
__device__ __align__(128) half  g_wc_hi[GROWS * KG];
__device__ __align__(128) half  g_wc_lo[GROWS * KG];
__device__ __align__(128) half  g_wo[(size_t)V_ * H_];
__device__ __align__(128) half  g_x_hi[KG * B_];
__device__ __align__(128) half  g_x_lo[KG * B_];
__device__ __align__(128) float g_part[(size_t)KSPL * GROWS * B_];   // 2 MB
__device__ __align__(128) float g_logits[B_ * V_];
__device__ __align__(128) float g_c[H_ * B_];
__device__ __align__(128) float g_hf[B_ * H_];
__device__ int    g_s[B_];
__device__ float2 g_cM[B_ * NBLK];    // (chunk max, chunk sumexp)
__device__ float4 g_cT[B_ * NBLK];    // (top1 val, top1 idx, top2 val, top2 idx)

// ---------------- helpers ----------------
__device__ __forceinline__ void cp16(void* sdst, const void* gsrc) {
  uint32_t d = (uint32_t)__cvta_generic_to_shared(sdst);
  asm volatile("cp.async.cg.shared.global [%0], [%1], 16;\n" :: "r"(d), "l"(gsrc));
}
#define CP_COMMIT() asm volatile("cp.async.commit_group;\n" ::: "memory")
#define CP_WAIT(n)  asm volatile("cp.async.wait_group %0;\n" :: "n"(n) : "memory")

__host__ __device__ inline void tf2x32(uint32_t k0, uint32_t k1, uint32_t x0, uint32_t x1,
                                       uint32_t &o0, uint32_t &o1) {
  uint32_t ks2 = k0 ^ k1 ^ 0x1BD11BDAu;
  x0 += k0; x1 += k1;
#define TF_R(r) do { x0 += x1; x1 = (x1 << (r)) | (x1 >> (32 - (r))); x1 ^= x0; } while (0)
  TF_R(13); TF_R(15); TF_R(26); TF_R(6);
  x0 += k1;  x1 += ks2 + 1u;
  TF_R(17); TF_R(29); TF_R(16); TF_R(24);
  x0 += ks2; x1 += k0 + 2u;
  TF_R(13); TF_R(15); TF_R(26); TF_R(6);
  x0 += k0;  x1 += k1 + 3u;
  TF_R(17); TF_R(29); TF_R(16); TF_R(24);
  x0 += k1;  x1 += ks2 + 4u;
  TF_R(13); TF_R(15); TF_R(26); TF_R(6);
  x0 += ks2; x1 += k0 + 5u;
#undef TF_R
  o0 = x0; o1 = x1;
}

__device__ __forceinline__ float gumbel_of(uint32_t k0, uint32_t k1, uint32_t i) {
  uint32_t a, b;
  tf2x32(k0, k1, 0u, i, a, b);
  uint32_t bits = a ^ b;
  float u = __uint_as_float((bits >> 9) | 0x3f800000u) - 1.0f;
  const float tiny = 1.17549435e-38f;
  float val = fmaxf(tiny, u * (1.0f - tiny) + tiny);
  return -logf(-logf(val));
}

__device__ __forceinline__ float sigm(float x) { return 1.0f / (1.0f + expf(-x)); }

__device__ __forceinline__ void merge2(float &v1, int &i1, float &v2, int &i2,
                                       float b1, int j1, float b2, int j2) {
  float n1, n2; int m1, m2;
  bool bf = (b1 > v1) || (b1 == v1 && j1 < i1);
  if (bf) { n1 = b1; m1 = j1; bool tk = (v1 > b2) || (v1 == b2 && i1 < j2);
            n2 = tk ? v1 : b2; m2 = tk ? i1 : j2; }
  else    { n1 = v1; m1 = i1; bool tk = (b1 > v2) || (b1 == v2 && j1 < i2);
            n2 = tk ? b1 : v2; m2 = tk ? j1 : i2; }
  v1 = n1; i1 = m1; v2 = n2; i2 = m2;
}

// ---------------- conversion / init ----------------
__global__ void k_conv_comb(const float* __restrict__ w_ih, const float* __restrict__ w_hh) {
  int np = GROWS * KG / 2;
  for (int p = blockIdx.x * blockDim.x + threadIdx.x; p < np; p += gridDim.x * blockDim.x) {
    int r = p >> 10, kp = (p & 1023) * 2;
    float v0, v1;
    if (kp < 1024) { v0 = __ldcs(w_ih + r * 1024 + kp); v1 = __ldcs(w_ih + r * 1024 + kp + 1); }
    else           { v0 = __ldcs(w_hh + r * 1024 + kp - 1024); v1 = __ldcs(w_hh + r * 1024 + kp - 1023); }
    half h0 = __float2half(v0), h1 = __float2half(v1);
    half2 hi = __halves2half2(h0, h1);
    half2 lo = __halves2half2(__float2half(v0 - __half2float(h0)),
                              __float2half(v1 - __half2float(h1)));
    size_t off = (size_t)r * KG + kp;
    *(half2*)&g_wc_hi[off] = hi;
    *(half2*)&g_wc_lo[off] = lo;
  }
}
__global__ void k_conv_wout(const float* __restrict__ w) {
  size_t np = (size_t)V_ * H_ / 2;
  for (size_t p = blockIdx.x * blockDim.x + threadIdx.x; p < np; p += (size_t)gridDim.x * blockDim.x) {
    float v0 = __ldcs(w + 2 * p), v1 = __ldcs(w + 2 * p + 1);
    *(half2*)&g_wo[2 * p] = __halves2half2(__float2half(v0), __float2half(v1));
  }
}
__global__ void k_init(const float* __restrict__ z, const int* __restrict__ sid,
                       const float* __restrict__ emb) {
  int idx = blockIdx.x * blockDim.x + threadIdx.x;
  if (idx < H_ * B_) {
    g_c[idx] = 0.0f;
    g_x_hi[H_ * B_ + idx] = __float2half(0.0f);
    g_x_lo[H_ * B_ + idx] = __float2half(0.0f);
    int b = idx & 31, hid = idx >> 5;
    g_hf[b * H_ + hid] = 0.0f;
  }
  if (idx < EMB_ * B_) {
    int b = idx & 31, k = idx >> 5;
    float v = z[b * EMB_ + k];
    half hi = __float2half(v);
    g_x_hi[(EMB_ + k) * B_ + b] = hi;
    g_x_lo[(EMB_ + k) * B_ + b] = __float2half(v - __half2float(hi));
    int tok = sid ? sid[0] : 0;
    float e = emb[tok * EMB_ + k];
    half ehi = __float2half(e);
    g_x_hi[k * B_ + b] = ehi;
    g_x_lo[k * B_ + b] = __float2half(e - __half2float(ehi));
  }
  if (idx < B_) g_s[idx] = sid ? sid[0] : 0;
}

// ---------------- gates GEMM.  grid (64, 4), block 128, KC=64, 3-stage -------
// virtual K = 4096: slices 0-1 = Whi vs BOTH xhi,xlo; slices 2-3 = Wlo vs xhi.
__global__ void k_gates(int t) {
  extern __shared__ half sm[];
  half* As = sm;
  half* Bh = sm + STG * GRB * ALD;
  half* Bl = Bh + STG * KC * BLD;
  int grp = blockIdx.x;
  if (t & 1) grp = (GROWS / GRB - 1) - grp;         // reversed scan on odd steps
  const int row0 = grp * GRB;
  const int ks = blockIdx.y;
  const int tid = threadIdx.x, w = tid >> 5;
  const bool hiPhase = ks < 2;
  const half* Wsrc = hiPhase ? g_wc_hi : g_wc_lo;
  const int kk0 = (ks & 1) * 1024;
  const int NCHK = 1024 / KC;   // 16

  wmma::fragment<wmma::accumulator, 16, 16, 16, float> fc0, fc1;
  wmma::fill_fragment(fc0, 0.0f); wmma::fill_fragment(fc1, 0.0f);

  auto issue = [&](int c) {
    int s = c % STG, kk = kk0 + c * KC;
    half* as = As + s * GRB * ALD;
#pragma unroll
    for (int j = 0; j < 4; j++) {
      int idx = tid + 128 * j, r = idx >> 3, cc = idx & 7;
      cp16(as + r * ALD + cc * 8, Wsrc + (size_t)(row0 + r) * KG + kk + cc * 8);
    }
    half* bh = Bh + s * KC * BLD;
    half* bl = Bl + s * KC * BLD;
#pragma unroll
    for (int j = 0; j < 2; j++) {
      int idx = tid + 128 * j, r = idx >> 2, cc = idx & 3;
      cp16(bh + r * BLD + cc * 8, g_x_hi + (kk + r) * B_ + cc * 8);
      if (hiPhase)
        cp16(bl + r * BLD + cc * 8, g_x_lo + (kk + r) * B_ + cc * 8);
    }
    CP_COMMIT();
  };

  issue(0); issue(1); issue(2);

  for (int c = 0; c < NCHK; c++) {
    if (c + STG < NCHK) { CP_WAIT(2); } else { CP_WAIT(0); }
    __syncthreads();
    int s = c % STG;
    half* as = As + s * GRB * ALD;
    half* bh = Bh + s * KC * BLD;
    half* bl = Bl + s * KC * BLD;
    wmma::fragment<wmma::matrix_a, 16, 16, 16, half, wmma::row_major> fa;
    wmma::fragment<wmma::matrix_b, 16, 16, 16, half, wmma::row_major> fb0, fb1;
#pragma unroll
    for (int k4 = 0; k4 < KC / 16; k4++) {
      wmma::load_matrix_sync(fa, as + (w * 16) * ALD + k4 * 16, ALD);
      wmma::load_matrix_sync(fb0, bh + (k4 * 16) * BLD + 0, BLD);
      wmma::load_matrix_sync(fb1, bh + (k4 * 16) * BLD + 16, BLD);
      wmma::mma_sync(fc0, fa, fb0, fc0);
      wmma::mma_sync(fc1, fa, fb1, fc1);
      if (hiPhase) {
        wmma::load_matrix_sync(fb0, bl + (k4 * 16) * BLD + 0, BLD);
        wmma::load_matrix_sync(fb1, bl + (k4 * 16) * BLD + 16, BLD);
        wmma::mma_sync(fc0, fa, fb0, fc0);
        wmma::mma_sync(fc1, fa, fb1, fc1);
      }
    }
    __syncthreads();
    if (c + STG < NCHK) issue(c + STG);
  }
  float* dst = g_part + ((size_t)ks * GROWS + row0 + w * 16) * B_;
  wmma::store_matrix_sync(dst, fc0, B_, wmma::mem_row_major);
  wmma::store_matrix_sync(dst + 16, fc1, B_, wmma::mem_row_major);
}

// ---------------- LSTM cell (+ split-K reduce) ----------------
__global__ void k_cell(const float* __restrict__ bias) {
  int idx = blockIdx.x * blockDim.x + threadIdx.x;
  if (idx >= H_ * B_) return;
  int b = idx & 31, hid = idx >> 5;
  float ig = 0.f, fg = 0.f, gg = 0.f, og = 0.f;
#pragma unroll
  for (int ks = 0; ks < KSPL; ks++) {
    const float* p = g_part + (size_t)ks * GROWS * B_;
    ig += __ldcs(p + hid * B_ + b);
    fg += __ldcs(p + (H_ + hid) * B_ + b);
    gg += __ldcs(p + (2 * H_ + hid) * B_ + b);
    og += __ldcs(p + (3 * H_ + hid) * B_ + b);
  }
  ig += bias[hid]; fg += bias[H_ + hid]; gg += bias[2 * H_ + hid]; og += bias[3 * H_ + hid];
  float c  = g_c[idx];
  float cn = sigm(fg) * c + sigm(ig) * tanhf(gg);
  float hn = sigm(og) * tanhf(cn);
  g_c[idx] = cn;
  g_hf[b * H_ + hid] = hn;
  half hi = __float2half(hn);
  g_x_hi[(H_ + hid) * B_ + b] = hi;
  g_x_lo[(H_ + hid) * B_ + b] = __float2half(hn - __half2float(hi));
}

// ------- logits GEMM + fused sampling stats.  grid 500, block 128, KC=64 -----
__global__ void k_logits(const float* __restrict__ bout, int t, uint32_t k0, uint32_t k1) {
  __shared__ half As[STG][LRB * ALD];
  __shared__ half Bs[STG][KC * BLD];
  int blk = blockIdx.x;
  if (t & 1) blk = (NBLK - 1) - blk;                // reversed scan on odd steps
  const int row0 = blk * LRB;
  const int tid = threadIdx.x, w = tid >> 5;
  const half* Bsrc = g_x_hi + H_ * B_;
  const int NCHK = H_ / KC;   // 16

  wmma::fragment<wmma::accumulator, 16, 16, 16, float> fc0, fc1;
  wmma::fill_fragment(fc0, 0.0f); wmma::fill_fragment(fc1, 0.0f);

  auto issue = [&](int c) {
    int s = c % STG, kk = c * KC;
#pragma unroll
    for (int j = 0; j < 4; j++) {
      int idx = tid + 128 * j, r = idx >> 3, cc = idx & 7;
      cp16(&As[s][r * ALD + cc * 8], g_wo + (size_t)(row0 + r) * H_ + kk + cc * 8);
    }
#pragma unroll
    for (int j = 0; j < 2; j++) {
      int idx = tid + 128 * j, r = idx >> 2, cc = idx & 3;
      cp16(&Bs[s][r * BLD + cc * 8], Bsrc + (kk + r) * B_ + cc * 8);
    }
    CP_COMMIT();
  };

  issue(0); issue(1); issue(2);

  for (int c = 0; c < NCHK; c++) {
    if (c + STG < NCHK) { CP_WAIT(2); } else { CP_WAIT(0); }
    __syncthreads();
    int s = c % STG;
    wmma::fragment<wmma::matrix_a, 16, 16, 16, half, wmma::row_major> fa;
    wmma::fragment<wmma::matrix_b, 16, 16, 16, half, wmma::row_major> fb0, fb1;
#pragma unroll
    for (int k4 = 0; k4 < KC / 16; k4++) {
      wmma::load_matrix_sync(fa, &As[s][(w * 16) * ALD + k4 * 16], ALD);
      wmma::load_matrix_sync(fb0, &Bs[s][(k4 * 16) * BLD + 0], BLD);
      wmma::load_matrix_sync(fb1, &Bs[s][(k4 * 16) * BLD + 16], BLD);
      wmma::mma_sync(fc0, fa, fb0, fc0);
      wmma::mma_sync(fc1, fa, fb1, fc1);
    }
    __syncthreads();
    if (c + STG < NCHK) issue(c + STG);
  }

  float* Ls = (float*)&As[0][0];
  __syncthreads();
  wmma::store_matrix_sync(&Ls[(w * 16) * 36 + 0],  fc0, 36, wmma::mem_row_major);
  wmma::store_matrix_sync(&Ls[(w * 16) * 36 + 16], fc1, 36, wmma::mem_row_major);
  __syncthreads();

  for (int i = tid; i < LRB * B_; i += 128) {
    int b = i >> 6, r = i & 63;
    float lb = Ls[r * 36 + b] + bout[row0 + r];
    Ls[r * 36 + b] = lb;
    __stcs(&g_logits[b * V_ + row0 + r], lb);
  }
  __syncthreads();

  int c = tid >> 2, sub = tid & 3;
  float m = -INFINITY, s = 0.0f, v1 = -INFINITY, v2 = -INFINITY;
  int i1 = 0x7fffffff, i2 = 0x7fffffff;
  for (int r = sub; r < LRB; r += 4) {
    float lb = Ls[r * 36 + c];
    if (lb > m) { s = s * expf(m - lb) + 1.0f; m = lb; } else s += expf(lb - m);
    int v = row0 + r;
    float tv = lb + gumbel_of(k0, k1, (uint32_t)(c * V_ + v));
    if (tv > v1 || (tv == v1 && v < i1)) { v2 = v1; i2 = i1; v1 = tv; i1 = v; }
    else if (tv > v2 || (tv == v2 && v < i2)) { v2 = tv; i2 = v; }
  }
#pragma unroll
  for (int o = 1; o <= 2; o <<= 1) {
    float om = __shfl_xor_sync(0xffffffffu, m, o);
    float os = __shfl_xor_sync(0xffffffffu, s, o);
    float M = fmaxf(m, om);
    s = s * expf(m - M) + os * expf(om - M); m = M;
    float b1 = __shfl_xor_sync(0xffffffffu, v1, o);
    int   j1 = __shfl_xor_sync(0xffffffffu, i1, o);
    float b2 = __shfl_xor_sync(0xffffffffu, v2, o);
    int   j2 = __shfl_xor_sync(0xffffffffu, i2, o);
    merge2(v1, i1, v2, i2, b1, j1, b2, j2);
  }
  if (sub == 0) {
    __stcs(&g_cM[c * NBLK + blk], make_float2(m, s));
    __stcs(&g_cT[c * NBLK + blk], make_float4(v1, __int_as_float(i1), v2, __int_as_float(i2)));
  }
}

// ---- post: p write (blocks 0..15, __stwt) + finalize (block 16). grid (17,32)
__global__ void k_post(const float* __restrict__ wout, const float* __restrict__ bout,
                       const float* __restrict__ emb,
                       float* outS, float* __restrict__ outP,
                       int t, uint32_t k0, uint32_t k1) {
  int c = blockIdx.x, b = blockIdx.y, tid = threadIdx.x;
  __shared__ float rm[256], rs[256];
  float m = -INFINITY, s = 0.0f;
  for (int j = tid; j < NBLK; j += 256) {
    float2 a = __ldcs(&g_cM[b * NBLK + j]);
    float M = fmaxf(m, a.x);
    s = s * expf(m - M) + a.y * expf(a.x - M); m = M;
  }
  rm[tid] = m; rs[tid] = s;
  __syncthreads();
  for (int off = 128; off; off >>= 1) {
    if (tid < off) {
      float mA = rm[tid], mB = rm[tid + off];
      float M = fmaxf(mA, mB);
      rm[tid] = M;
      rs[tid] = rs[tid] * expf(mA - M) + rs[tid + off] * expf(mB - M);
    }
    __syncthreads();
  }
  float gm = rm[0], ginv = 1.0f / rs[0];
  __syncthreads();

  if (c < NPB) {
    int vbeg = c * VCH;
    float* op = outP + ((size_t)b * T_ + t) * V_;
    for (int v = vbeg + tid; v < vbeg + VCH; v += 256)
      __stwt(op + v, expf(__ldcs(&g_logits[b * V_ + v]) - gm) * ginv);   // WT: no L2 pollution
    return;
  }

  // finalize: global top-1 of approx (l+g), then exact recompute of near-ties
  __shared__ float r1[256];
  __shared__ int   q1[256];
  float v1 = -INFINITY; int i1 = 0x7fffffff;
  for (int j = tid; j < NBLK; j += 256) {
    float4 a = __ldcs(&g_cT[b * NBLK + j]);
    float d2 = -INFINITY; int di = 0x7fffffff;
    merge2(v1, i1, d2, di, a.x, __float_as_int(a.y), a.z, __float_as_int(a.w));
  }
  r1[tid] = v1; q1[tid] = i1;
  __syncthreads();
  for (int off = 128; off; off >>= 1) {
    if (tid < off) {
      float bv = r1[tid + off]; int bi = q1[tid + off];
      if (bv > r1[tid] || (bv == r1[tid] && bi < q1[tid])) { r1[tid] = bv; q1[tid] = bi; }
    }
    __syncthreads();
  }
  float gtop = r1[0];
  __syncthreads();

  __shared__ int ncand;
  __shared__ int cands[64];
  __shared__ double cval[64];
  __shared__ int    cidx[64];
  __shared__ int    s_tok;
  if (tid == 0) ncand = 0;
  __syncthreads();
  float thr = gtop - DELTA;
  for (int j = tid; j < NBLK; j += 256) {
    float4 a = __ldcs(&g_cT[b * NBLK + j]);
    if (a.x >= thr) { int p = atomicAdd(&ncand, 1); if (p < 64) cands[p] = __float_as_int(a.y); }
    if (a.z >= thr) { int p = atomicAdd(&ncand, 1); if (p < 64) cands[p] = __float_as_int(a.w); }
  }
  __syncthreads();
  int n = ncand < 64 ? ncand : 64;
  int w = tid >> 5, lane = tid & 31;
  for (int ci = w; ci < n; ci += 8) {
    int v = cands[ci];
    const float4* wr4 = (const float4*)(wout + (size_t)v * H_);
    const float4* hr4 = (const float4*)(g_hf + b * H_);
    double acc = 0.0;
#pragma unroll
    for (int j = 0; j < 8; j++) {
      float4 a4 = __ldg(wr4 + lane + 32 * j);
      float4 b4 = hr4[lane + 32 * j];
      acc += (double)a4.x * b4.x + (double)a4.y * b4.y
           + (double)a4.z * b4.z + (double)a4.w * b4.w;
    }
    for (int o = 16; o; o >>= 1) acc += __shfl_down_sync(0xffffffffu, acc, o);
    if (lane == 0) {
      cval[ci] = acc + (double)bout[v] + (double)gumbel_of(k0, k1, (uint32_t)(b * V_ + v));
      cidx[ci] = v;
    }
  }
  __syncthreads();
  if (tid == 0) {
    double bv = -1e300; int bi = 0x7fffffff;
    for (int ci = 0; ci < n; ci++)
      if (cval[ci] > bv || (cval[ci] == bv && cidx[ci] < bi)) { bv = cval[ci]; bi = cidx[ci]; }
    s_tok = bi;
    g_s[b] = bi;
    if (outS) outS[b * T_ + t] = (float)bi;
  }
  __syncthreads();
  int tok = s_tok;
  for (int k = tid; k < EMB_; k += 256) {
    float val = emb[tok * EMB_ + k];
    half hi = __float2half(val);
    g_x_hi[k * B_ + b] = hi;
    g_x_lo[k * B_ + b] = __float2half(val - __half2float(hi));
  }
}

// ---------------- host ----------------
extern "C" void kernel_launch(void* const* d_in, const int* in_sizes, int n_in,
                              void* d_out, int out_size) {
  const float* z     = (const float*)d_in[0];
  const float* emb   = (const float*)d_in[1];
  const float* w_ih  = (const float*)d_in[2];
  const float* w_hh  = (const float*)d_in[3];
  const float* bias  = (const float*)d_in[4];
  const float* w_out = (const float*)d_in[5];
  const float* b_out = (const float*)d_in[6];
  const int*   sid   = (n_in > 7) ? (const int*)d_in[7] : nullptr;

  float* out  = (float*)d_out;
  float* outS = out;
  float* outP = out + B_ * T_;
  if (out_size == B_ * T_ * V_) { outS = nullptr; outP = out; }

  const int gatesSmem = (STG * GRB * ALD + 2 * STG * KC * BLD) * (int)sizeof(half);
  cudaFuncSetAttribute(k_gates, cudaFuncAttributeMaxDynamicSharedMemorySize, gatesSmem);

  k_conv_comb<<<512, 256>>>(w_ih, w_hh);
  k_conv_wout<<<2048, 256>>>(w_out);
  k_init<<<(H_ * B_ + 255) / 256, 256>>>(z, sid, emb);

  for (int t = 0; t < T_; ++t) {
    uint32_t fk0, fk1;
    tf2x32(0u, 42u, 0u, (uint32_t)t, fk0, fk1);
    k_gates<<<dim3(GROWS / GRB, KSPL), 128, gatesSmem>>>(t);
    k_cell<<<(H_ * B_ + 255) / 256, 256>>>(bias);
    k_logits<<<NBLK, 128>>>(b_out, t, fk0, fk1);
    k_post<<<dim3(NPB + 1, B_), 256>>>(w_out, b_out, emb, outS, outP, t, fk0, fk1);
  }
}